// round 1
// baseline (speedup 1.0000x reference)
#include <cuda_runtime.h>
#include <math.h>

#define BDIM 16
#define SEQ  1024
#define HIDN 768
#define NH   12
#define HD   64
#define NBH  (BDIM*NH)   // 192

// Scratch (allocation-free rule: __device__ globals)
__device__ float g_q[(size_t)NBH*SEQ*HD];
__device__ float g_k[(size_t)NBH*SEQ*HD];
__device__ float g_v[(size_t)NBH*SEQ*HD];
__device__ float g_o[(size_t)NBH*SEQ*HD];

// ---------------------------------------------------------------------------
// Fused QKV projection: Y = x @ W^T + b, then bias + RoPE (+scale for Q),
// written to [B,H,S,D] scratch. grid = (256, 12, 3), 256 threads.
// BM=64, BN=64, BK=16, 4x4 microtile per thread.
// ---------------------------------------------------------------------------
__global__ __launch_bounds__(256) void qkv_kernel(
    const float* __restrict__ x,
    const float* __restrict__ Wq, const float* __restrict__ bq,
    const float* __restrict__ Wk, const float* __restrict__ bk,
    const float* __restrict__ Wv, const float* __restrict__ bv,
    const float* __restrict__ cosc, const float* __restrict__ sinc)
{
    __shared__ float xs[16][68];
    __shared__ float wsm[16][68];

    const int z = blockIdx.z;
    const float* W    = (z==0) ? Wq : (z==1) ? Wk : Wv;
    const float* bias = (z==0) ? bq : (z==1) ? bk : bv;
    float* outp       = (z==0) ? g_q : (z==1) ? g_k : g_v;

    const int row0 = blockIdx.x * 64;
    const int h    = blockIdx.y;          // output col block == head
    const int tid  = threadIdx.x;
    const int ti = tid >> 4, tj = tid & 15;
    const int lr = tid >> 2, lk = (tid & 3) << 2;

    float acc[4][4];
    #pragma unroll
    for (int a=0;a<4;a++)
        #pragma unroll
        for (int b=0;b<4;b++) acc[a][b]=0.f;

    for (int k0 = 0; k0 < HIDN; k0 += 16) {
        float4 xa = *(const float4*)(x + (size_t)(row0+lr)*HIDN + k0 + lk);
        float4 wa = *(const float4*)(W + (size_t)(h*64+lr)*HIDN + k0 + lk);
        __syncthreads();
        xs[lk+0][lr]=xa.x; xs[lk+1][lr]=xa.y; xs[lk+2][lr]=xa.z; xs[lk+3][lr]=xa.w;
        wsm[lk+0][lr]=wa.x; wsm[lk+1][lr]=wa.y; wsm[lk+2][lr]=wa.z; wsm[lk+3][lr]=wa.w;
        __syncthreads();
        #pragma unroll
        for (int kk=0; kk<16; kk++) {
            float4 av  = *(const float4*)&xs[kk][ti<<2];
            float4 bv4 = *(const float4*)&wsm[kk][tj<<2];
            acc[0][0]+=av.x*bv4.x; acc[0][1]+=av.x*bv4.y; acc[0][2]+=av.x*bv4.z; acc[0][3]+=av.x*bv4.w;
            acc[1][0]+=av.y*bv4.x; acc[1][1]+=av.y*bv4.y; acc[1][2]+=av.y*bv4.z; acc[1][3]+=av.y*bv4.w;
            acc[2][0]+=av.z*bv4.x; acc[2][1]+=av.z*bv4.y; acc[2][2]+=av.z*bv4.z; acc[2][3]+=av.z*bv4.w;
            acc[3][0]+=av.w*bv4.x; acc[3][1]+=av.w*bv4.y; acc[3][2]+=av.w*bv4.z; acc[3][3]+=av.w*bv4.w;
        }
    }

    float bj[4];
    #pragma unroll
    for (int c=0;c<4;c++) bj[c] = bias[h*64 + (tj<<2) + c];

    #pragma unroll
    for (int r=0;r<4;r++){
        int grow = row0 + (ti<<2) + r;
        int b_ = grow >> 10;
        int s_ = grow & 1023;
        int d0 = tj << 2;
        float v0 = acc[r][0]+bj[0], v1 = acc[r][1]+bj[1];
        float v2 = acc[r][2]+bj[2], v3 = acc[r][3]+bj[3];
        float4 outv;
        if (z == 2) {
            outv = make_float4(v0,v1,v2,v3);
        } else {
            int t0 = d0 >> 1;   // pair index (d0 is even)
            float c0 = cosc[s_*32 + t0],   sn0 = sinc[s_*32 + t0];
            float c1 = cosc[s_*32 + t0+1], sn1 = sinc[s_*32 + t0+1];
            float sc = (z==0) ? 0.125f : 1.0f;   // 1/sqrt(64) for Q
            outv.x = (v0*c0 - v1*sn0)*sc;
            outv.y = (v1*c0 + v0*sn0)*sc;
            outv.z = (v2*c1 - v3*sn1)*sc;
            outv.w = (v3*c1 + v2*sn1)*sc;
        }
        *(float4*)(outp + ((size_t)(b_*NH + h)*SEQ + s_)*HD + d0) = outv;
    }
}

// ---------------------------------------------------------------------------
// RSE attention. CTA = 128 query rows of one (b,h); sequential scan over 32
// key blocks of 32 keys. 256 threads: i=tid>>3 owns rows 4i..4i+3,
// j=tid&7 owns logits cols 4j..4j+3 and PV dims {4j..4j+3, 4j+32..4j+35}.
// rem / l / m are replicated across the 8 lanes of each row group via shfl.
// ---------------------------------------------------------------------------
#define ATTN_SMEM ((64*128 + 64*32 + 32*64 + 128*36)*4)

__global__ __launch_bounds__(256) void attn_kernel(const float* __restrict__ lam_p)
{
    extern __shared__ float smbuf[];
    float* qs = smbuf;            // [d][m]  64 x 128
    float* ks = qs + 64*128;      // [d][n]  64 x 32
    float* vs = ks + 64*32;       // [n][d]  32 x 64
    float* ws = vs + 32*64;       // [m][n]  128 x 36 (padded)

    const int bh = blockIdx.y;
    const int m0 = blockIdx.x * 128;
    const int tid = threadIdx.x;
    const int i = tid >> 3;
    const int j = tid & 7;
    const float lam = *lam_p;

    const float* qg = g_q + (size_t)bh*SEQ*HD;
    const float* kg = g_k + (size_t)bh*SEQ*HD;
    const float* vg = g_v + (size_t)bh*SEQ*HD;

    // Load Q tile transposed into qs[d][m]
    #pragma unroll
    for (int it=0; it<8; it++){
        int idx = tid + it*256;           // 0..2047
        int m = idx & 127, d4 = idx >> 7; // d4: 0..15
        float4 qv = *(const float4*)(qg + (size_t)(m0+m)*HD + (d4<<2));
        qs[(d4*4+0)*128 + m] = qv.x;
        qs[(d4*4+1)*128 + m] = qv.y;
        qs[(d4*4+2)*128 + m] = qv.z;
        qs[(d4*4+3)*128 + m] = qv.w;
    }

    float rem[4], li[4], mi[4];
    #pragma unroll
    for (int r=0;r<4;r++){ rem[r]=1.f; li[r]=0.f; mi[r]=-INFINITY; }
    float acc[4][8];
    #pragma unroll
    for (int r=0;r<4;r++)
        #pragma unroll
        for (int c=0;c<8;c++) acc[r][c]=0.f;

    for (int nb=0; nb<32; nb++){
        __syncthreads();
        // Load K (transposed) and V tiles
        #pragma unroll
        for (int it=0; it<2; it++){
            int idx = tid + it*256;            // 0..511
            int n = idx & 31, d4 = idx >> 5;   // d4: 0..15
            float4 kv = *(const float4*)(kg + (size_t)(nb*32+n)*HD + (d4<<2));
            ks[(d4*4+0)*32+n]=kv.x; ks[(d4*4+1)*32+n]=kv.y;
            ks[(d4*4+2)*32+n]=kv.z; ks[(d4*4+3)*32+n]=kv.w;
            int n2 = idx >> 4, d42 = idx & 15;
            float4 vv = *(const float4*)(vg + (size_t)(nb*32+n2)*HD + (d42<<2));
            *(float4*)&vs[n2*64 + (d42<<2)] = vv;
        }
        __syncthreads();

        // logits microtile 4x4
        float lg[4][4];
        #pragma unroll
        for (int r=0;r<4;r++)
            #pragma unroll
            for (int c=0;c<4;c++) lg[r][c]=0.f;
        #pragma unroll 8
        for (int d=0; d<64; d++){
            float4 qv = *(const float4*)&qs[d*128 + (i<<2)];
            float4 kv = *(const float4*)&ks[d*32  + (j<<2)];
            lg[0][0]+=qv.x*kv.x; lg[0][1]+=qv.x*kv.y; lg[0][2]+=qv.x*kv.z; lg[0][3]+=qv.x*kv.w;
            lg[1][0]+=qv.y*kv.x; lg[1][1]+=qv.y*kv.y; lg[1][2]+=qv.y*kv.z; lg[1][3]+=qv.y*kv.w;
            lg[2][0]+=qv.z*kv.x; lg[2][1]+=qv.z*kv.y; lg[2][2]+=qv.z*kv.z; lg[2][3]+=qv.z*kv.w;
            lg[3][0]+=qv.w*kv.x; lg[3][1]+=qv.w*kv.y; lg[3][2]+=qv.w*kv.z; lg[3][3]+=qv.w*kv.w;
        }

        float cs[4], rmax[4];
        #pragma unroll
        for (int r=0;r<4;r++){ cs[r]=0.f; rmax[r]=-INFINITY; }

        #pragma unroll
        for (int r=0;r<4;r++){
            float sq = (float)(m0 + (i<<2) + r);
            #pragma unroll
            for (int jj=0;jj<4;jj++){
                float sk = (float)(nb*32 + (j<<2) + jj);
                float raw = lg[r][jj] - lam*fabsf(sq - sk);
                rmax[r] = fmaxf(rmax[r], raw);
                float cl = fminf(fmaxf(raw, -20.f), 20.f);
                float w  = rem[r] / (1.f + __expf(-cl));
                ws[((i<<2)+r)*36 + (j<<2)+jj] = w;
                cs[r] += w;
            }
        }
        // reduce consumed and rowmax across the 8 j-lanes (replicated result)
        #pragma unroll
        for (int ofs=4; ofs>0; ofs>>=1){
            #pragma unroll
            for (int r=0;r<4;r++){
                cs[r]  += __shfl_xor_sync(0xffffffffu, cs[r], ofs);
                rmax[r] = fmaxf(rmax[r], __shfl_xor_sync(0xffffffffu, rmax[r], ofs));
            }
        }
        #pragma unroll
        for (int r=0;r<4;r++){
            float mn = fmaxf(mi[r], rmax[r]);
            li[r]  = li[r]*exp2f(mi[r]-mn) + cs[r];
            mi[r]  = mn;
            rem[r] = fmaxf(rem[r]*(1.f - cs[r]), 1e-6f);
        }
        __syncthreads();

        // acc += w @ V
        #pragma unroll 8
        for (int n=0;n<32;n++){
            float w0 = ws[((i<<2)+0)*36+n];
            float w1 = ws[((i<<2)+1)*36+n];
            float w2 = ws[((i<<2)+2)*36+n];
            float w3 = ws[((i<<2)+3)*36+n];
            float4 va = *(const float4*)&vs[n*64 + (j<<2)];
            float4 vb = *(const float4*)&vs[n*64 + (j<<2) + 32];
            acc[0][0]+=w0*va.x; acc[0][1]+=w0*va.y; acc[0][2]+=w0*va.z; acc[0][3]+=w0*va.w;
            acc[1][0]+=w1*va.x; acc[1][1]+=w1*va.y; acc[1][2]+=w1*va.z; acc[1][3]+=w1*va.w;
            acc[2][0]+=w2*va.x; acc[2][1]+=w2*va.y; acc[2][2]+=w2*va.z; acc[2][3]+=w2*va.w;
            acc[3][0]+=w3*va.x; acc[3][1]+=w3*va.y; acc[3][2]+=w3*va.z; acc[3][3]+=w3*va.w;
            acc[0][4]+=w0*vb.x; acc[0][5]+=w0*vb.y; acc[0][6]+=w0*vb.z; acc[0][7]+=w0*vb.w;
            acc[1][4]+=w1*vb.x; acc[1][5]+=w1*vb.y; acc[1][6]+=w1*vb.z; acc[1][7]+=w1*vb.w;
            acc[2][4]+=w2*vb.x; acc[2][5]+=w2*vb.y; acc[2][6]+=w2*vb.z; acc[2][7]+=w2*vb.w;
            acc[3][4]+=w3*vb.x; acc[3][5]+=w3*vb.y; acc[3][6]+=w3*vb.z; acc[3][7]+=w3*vb.w;
        }
    }

    float* og = g_o + (size_t)bh*SEQ*HD;
    #pragma unroll
    for (int r=0;r<4;r++){
        float inv = 1.f / fmaxf(li[r], 1e-6f);
        size_t base = (size_t)(m0 + (i<<2) + r)*HD;
        float4 o1 = make_float4(acc[r][0]*inv, acc[r][1]*inv, acc[r][2]*inv, acc[r][3]*inv);
        float4 o2 = make_float4(acc[r][4]*inv, acc[r][5]*inv, acc[r][6]*inv, acc[r][7]*inv);
        *(float4*)(og + base + (j<<2))      = o1;
        *(float4*)(og + base + (j<<2) + 32) = o2;
    }
}

// ---------------------------------------------------------------------------
// Output projection: y = ctx @ Wo^T + bo, ctx gathered from g_o [B,H,S,D].
// ---------------------------------------------------------------------------
__global__ __launch_bounds__(256) void out_kernel(
    const float* __restrict__ Wo, const float* __restrict__ bo,
    float* __restrict__ y)
{
    __shared__ float xs[16][68];
    __shared__ float wsm[16][68];

    const int row0 = blockIdx.x * 64;
    const int cb   = blockIdx.y;          // output col block
    const int tid  = threadIdx.x;
    const int ti = tid >> 4, tj = tid & 15;
    const int lr = tid >> 2, lk = (tid & 3) << 2;

    float acc[4][4];
    #pragma unroll
    for (int a=0;a<4;a++)
        #pragma unroll
        for (int b=0;b<4;b++) acc[a][b]=0.f;

    const int grow_l = row0 + lr;
    const int b_l = grow_l >> 10, s_l = grow_l & 1023;

    for (int k0 = 0; k0 < HIDN; k0 += 16) {
        int kcol = k0 + lk;
        int hh = kcol >> 6, dd = kcol & 63;
        float4 xa = *(const float4*)(g_o + ((size_t)(b_l*NH+hh)*SEQ + s_l)*HD + dd);
        float4 wa = *(const float4*)(Wo + (size_t)(cb*64+lr)*HIDN + k0 + lk);
        __syncthreads();
        xs[lk+0][lr]=xa.x; xs[lk+1][lr]=xa.y; xs[lk+2][lr]=xa.z; xs[lk+3][lr]=xa.w;
        wsm[lk+0][lr]=wa.x; wsm[lk+1][lr]=wa.y; wsm[lk+2][lr]=wa.z; wsm[lk+3][lr]=wa.w;
        __syncthreads();
        #pragma unroll
        for (int kk=0; kk<16; kk++) {
            float4 av  = *(const float4*)&xs[kk][ti<<2];
            float4 bv4 = *(const float4*)&wsm[kk][tj<<2];
            acc[0][0]+=av.x*bv4.x; acc[0][1]+=av.x*bv4.y; acc[0][2]+=av.x*bv4.z; acc[0][3]+=av.x*bv4.w;
            acc[1][0]+=av.y*bv4.x; acc[1][1]+=av.y*bv4.y; acc[1][2]+=av.y*bv4.z; acc[1][3]+=av.y*bv4.w;
            acc[2][0]+=av.z*bv4.x; acc[2][1]+=av.z*bv4.y; acc[2][2]+=av.z*bv4.z; acc[2][3]+=av.z*bv4.w;
            acc[3][0]+=av.w*bv4.x; acc[3][1]+=av.w*bv4.y; acc[3][2]+=av.w*bv4.z; acc[3][3]+=av.w*bv4.w;
        }
    }

    float bj[4];
    #pragma unroll
    for (int c=0;c<4;c++) bj[c] = bo[cb*64 + (tj<<2) + c];

    #pragma unroll
    for (int r=0;r<4;r++){
        int grow = row0 + (ti<<2) + r;
        float4 outv = make_float4(acc[r][0]+bj[0], acc[r][1]+bj[1],
                                  acc[r][2]+bj[2], acc[r][3]+bj[3]);
        *(float4*)(y + (size_t)grow*HIDN + cb*64 + (tj<<2)) = outv;
    }
}

// ---------------------------------------------------------------------------
extern "C" void kernel_launch(void* const* d_in, const int* in_sizes, int n_in,
                              void* d_out, int out_size)
{
    const float* x    = (const float*)d_in[0];
    const float* Wq   = (const float*)d_in[1];
    const float* bq   = (const float*)d_in[2];
    const float* Wk   = (const float*)d_in[3];
    const float* bk   = (const float*)d_in[4];
    const float* Wv   = (const float*)d_in[5];
    const float* bv   = (const float*)d_in[6];
    const float* Wo   = (const float*)d_in[7];
    const float* bo   = (const float*)d_in[8];
    const float* lam  = (const float*)d_in[9];
    const float* cosc = (const float*)d_in[10];
    const float* sinc = (const float*)d_in[11];
    float* y = (float*)d_out;

    cudaFuncSetAttribute(attn_kernel, cudaFuncAttributeMaxDynamicSharedMemorySize, ATTN_SMEM);

    dim3 g1(BDIM*SEQ/64, NH, 3);
    qkv_kernel<<<g1, 256>>>(x, Wq, bq, Wk, bk, Wv, bv, cosc, sinc);

    dim3 g2(SEQ/128, NBH);
    attn_kernel<<<g2, 256, ATTN_SMEM>>>(lam);

    dim3 g3(BDIM*SEQ/64, NH);
    out_kernel<<<g3, 256>>>(Wo, bo, y);
}

// round 5
// speedup vs baseline: 2.2727x; 2.2727x over previous
#include <cuda_runtime.h>
#include <cuda_fp16.h>
#include <math.h>
#include <stdint.h>

#define BDIM 16
#define SEQ  1024
#define HIDN 768
#define NH   12
#define HD   64
#define NBH  (BDIM*NH)   // 192

// Scratch (allocation-free rule: __device__ globals)
__device__ float g_q[(size_t)NBH*SEQ*HD];
__device__ float g_k[(size_t)NBH*SEQ*HD];
__device__ float g_v[(size_t)NBH*SEQ*HD];
__device__ float g_o[(size_t)NBH*SEQ*HD];

// m16n8k16 fp16 MMA, fp32 accum. A row-major (16xk16), B col-major (k16x8).
// g=lane>>2, q=lane&3.
// A: a0=(g,2q:2q+1) a1=(g+8,2q:2q+1) a2=(g,2q+8:2q+9) a3=(g+8,2q+8:2q+9)
// B: b0=(k=2q:2q+1,n=g) b1=(k=2q+8:2q+9,n=g)
// C: c0=(g,2q) c1=(g,2q+1) c2=(g+8,2q) c3=(g+8,2q+1)
__device__ __forceinline__ void mma_f16(float c[4],
    uint32_t a0, uint32_t a1, uint32_t a2, uint32_t a3,
    uint32_t b0, uint32_t b1)
{
    asm volatile(
        "mma.sync.aligned.m16n8k16.row.col.f32.f16.f16.f32 "
        "{%0,%1,%2,%3},{%4,%5,%6,%7},{%8,%9},{%0,%1,%2,%3};\n"
        : "+f"(c[0]), "+f"(c[1]), "+f"(c[2]), "+f"(c[3])
        : "r"(a0), "r"(a1), "r"(a2), "r"(a3), "r"(b0), "r"(b1));
}

__device__ __forceinline__ uint32_t packh(__half a, __half b){
    __half2 h = __halves2half2(a, b);
    return *(uint32_t*)&h;
}

// split (x,y) into hi/lo half2 pairs: x = hi + lo with ~22-bit combined mantissa
__device__ __forceinline__ void split_pair(float x, float y, uint32_t &hi, uint32_t &lo){
    __half hx = __float2half_rn(x);
    __half hy = __float2half_rn(y);
    __half lx = __float2half_rn(x - __half2float(hx));
    __half ly = __float2half_rn(y - __half2float(hy));
    hi = packh(hx, hy);
    lo = packh(lx, ly);
}

#define QS 20   // row stride (u32) for 16-half2 rows; g*20%32 permutes banks
#define KS 36   // row stride (u32) for 32-half2 rows; g*36%32 = 4g permutes banks

// ---------------------------------------------------------------------------
// Fused QKV projection (split-fp16 MMA): Y = x @ W^T + b, + RoPE (+scale for Q).
// grid = (128, 12, 3), 256 threads. BM=128, BN=64, BK=32.
// 8 warps as 4(m) x 2(n); warp tile 32x32.
// ---------------------------------------------------------------------------
__global__ __launch_bounds__(256) void qkv_kernel(
    const float* __restrict__ x,
    const float* __restrict__ Wq, const float* __restrict__ bq,
    const float* __restrict__ Wk, const float* __restrict__ bk,
    const float* __restrict__ Wv, const float* __restrict__ bv,
    const float* __restrict__ cosc, const float* __restrict__ sinc)
{
    __shared__ uint32_t xh[128*QS], xl[128*QS];
    __shared__ uint32_t wh[64*QS],  wl[64*QS];

    const int z = blockIdx.z;
    const float* W    = (z==0) ? Wq : (z==1) ? Wk : Wv;
    const float* bias = (z==0) ? bq : (z==1) ? bk : bv;
    float* outp       = (z==0) ? g_q : (z==1) ? g_k : g_v;

    const int row0 = blockIdx.x * 128;
    const int h    = blockIdx.y;
    const int tid  = threadIdx.x;
    const int w    = tid >> 5, lane = tid & 31;
    const int g    = lane >> 2, q = lane & 3;
    const int warpm = w >> 1, warpn = w & 1;

    float c[2][4][4];
    #pragma unroll
    for (int mf=0; mf<2; mf++)
        #pragma unroll
        for (int nf=0; nf<4; nf++)
            #pragma unroll
            for (int e=0; e<4; e++) c[mf][nf][e]=0.f;

    for (int k0 = 0; k0 < HIDN; k0 += 32) {
        #pragma unroll
        for (int it=0; it<4; it++){
            int l = tid + it*256;           // 0..1023
            int m = l >> 3, kq = l & 7;
            float4 v = *(const float4*)(x + (size_t)(row0+m)*HIDN + k0 + kq*4);
            uint32_t h0,l0,h1,l1;
            split_pair(v.x, v.y, h0, l0);
            split_pair(v.z, v.w, h1, l1);
            xh[m*QS + kq*2  ] = h0; xh[m*QS + kq*2+1] = h1;
            xl[m*QS + kq*2  ] = l0; xl[m*QS + kq*2+1] = l1;
        }
        #pragma unroll
        for (int it=0; it<2; it++){
            int l = tid + it*256;           // 0..511
            int n = l >> 3, kq = l & 7;
            float4 v = *(const float4*)(W + (size_t)(h*64+n)*HIDN + k0 + kq*4);
            uint32_t h0,l0,h1,l1;
            split_pair(v.x, v.y, h0, l0);
            split_pair(v.z, v.w, h1, l1);
            wh[n*QS + kq*2  ] = h0; wh[n*QS + kq*2+1] = h1;
            wl[n*QS + kq*2  ] = l0; wl[n*QS + kq*2+1] = l1;
        }
        __syncthreads();
        #pragma unroll
        for (int kf=0; kf<2; kf++){         // two k16 steps
            uint32_t ah[2][4], al[2][4];
            #pragma unroll
            for (int mf=0; mf<2; mf++){
                int r = warpm*32 + mf*16 + g;
                ah[mf][0]=xh[(r  )*QS + kf*8 + q  ]; ah[mf][1]=xh[(r+8)*QS + kf*8 + q  ];
                ah[mf][2]=xh[(r  )*QS + kf*8 + q+4]; ah[mf][3]=xh[(r+8)*QS + kf*8 + q+4];
                al[mf][0]=xl[(r  )*QS + kf*8 + q  ]; al[mf][1]=xl[(r+8)*QS + kf*8 + q  ];
                al[mf][2]=xl[(r  )*QS + kf*8 + q+4]; al[mf][3]=xl[(r+8)*QS + kf*8 + q+4];
            }
            uint32_t bh[4][2], bl[4][2];
            #pragma unroll
            for (int nf=0; nf<4; nf++){
                int n = warpn*32 + nf*8 + g;
                bh[nf][0]=wh[n*QS + kf*8 + q]; bh[nf][1]=wh[n*QS + kf*8 + q+4];
                bl[nf][0]=wl[n*QS + kf*8 + q]; bl[nf][1]=wl[n*QS + kf*8 + q+4];
            }
            #pragma unroll
            for (int mf=0; mf<2; mf++)
                #pragma unroll
                for (int nf=0; nf<4; nf++){
                    mma_f16(c[mf][nf], ah[mf][0],ah[mf][1],ah[mf][2],ah[mf][3], bh[nf][0],bh[nf][1]);
                    mma_f16(c[mf][nf], ah[mf][0],ah[mf][1],ah[mf][2],ah[mf][3], bl[nf][0],bl[nf][1]);
                    mma_f16(c[mf][nf], al[mf][0],al[mf][1],al[mf][2],al[mf][3], bh[nf][0],bh[nf][1]);
                }
        }
        __syncthreads();
    }

    const float sc = (z==0) ? 0.125f : 1.0f;
    #pragma unroll
    for (int nf=0; nf<4; nf++){
        int col = warpn*32 + nf*8 + 2*q;        // even
        float b0 = bias[h*64 + col], b1 = bias[h*64 + col + 1];
        int t = col >> 1;                        // rope pair index
        #pragma unroll
        for (int mf=0; mf<2; mf++){
            #pragma unroll
            for (int half=0; half<2; half++){
                int row = row0 + warpm*32 + mf*16 + g + half*8;
                int b_ = row >> 10, s_ = row & 1023;
                float v0 = c[mf][nf][half*2+0] + b0;
                float v1 = c[mf][nf][half*2+1] + b1;
                float2 outv;
                if (z == 2) {
                    outv = make_float2(v0, v1);
                } else {
                    float cs_ = cosc[s_*32 + t], sn_ = sinc[s_*32 + t];
                    outv.x = (v0*cs_ - v1*sn_)*sc;
                    outv.y = (v1*cs_ + v0*sn_)*sc;
                }
                *(float2*)(outp + ((size_t)(b_*NH + h)*SEQ + s_)*HD + col) = outv;
            }
        }
    }
}

// ---------------------------------------------------------------------------
// RSE attention (split-fp16 MMA). CTA = 128 query rows of one (b,h), 8 warps.
// Warp w owns rows 16w..16w+15; Q hi/lo A-frags live in registers.
// Sequential scan over 32 key blocks; rem/l/m replicated across lane-quads.
// ---------------------------------------------------------------------------
__global__ __launch_bounds__(256) void attn_kernel(const float* __restrict__ lam_p)
{
    __shared__ uint32_t kh[32*KS],  kl[32*KS];    // K [key][d-half2], QK^T B operand
    __shared__ uint32_t vth[64*QS], vtl[64*QS];   // V^T [d][key-half2], PV B operand
    __shared__ uint32_t wsh[128*QS], wsl[128*QS]; // w [row][key-half2], PV A operand

    const int bh = blockIdx.y;
    const int m0 = blockIdx.x * 128;
    const int tid = threadIdx.x;
    const int w = tid >> 5, lane = tid & 31;
    const int g = lane >> 2, q = lane & 3;
    const float lam = *lam_p;

    const float* qg = g_q + (size_t)bh*SEQ*HD;
    const float* kg = g_k + (size_t)bh*SEQ*HD;
    const float* vg = g_v + (size_t)bh*SEQ*HD;

    // Q fragments (hi/lo): rows m0+16w+{g,g+8}, k-steps kf*16
    uint32_t qah[4][4], qal[4][4];
    {
        const int r0 = m0 + 16*w + g;
        #pragma unroll
        for (int kf=0; kf<4; kf++){
            float2 q0 = *(const float2*)(qg + (size_t)(r0  )*HD + kf*16 + 2*q    );
            float2 q1 = *(const float2*)(qg + (size_t)(r0+8)*HD + kf*16 + 2*q    );
            float2 q2 = *(const float2*)(qg + (size_t)(r0  )*HD + kf*16 + 2*q + 8);
            float2 q3 = *(const float2*)(qg + (size_t)(r0+8)*HD + kf*16 + 2*q + 8);
            split_pair(q0.x, q0.y, qah[kf][0], qal[kf][0]);
            split_pair(q1.x, q1.y, qah[kf][1], qal[kf][1]);
            split_pair(q2.x, q2.y, qah[kf][2], qal[kf][2]);
            split_pair(q3.x, q3.y, qah[kf][3], qal[kf][3]);
        }
    }

    float rem0=1.f, rem1=1.f, li0=0.f, li1=0.f, mi0=-INFINITY, mi1=-INFINITY;
    float acc[8][4];
    #pragma unroll
    for (int nf=0; nf<8; nf++)
        #pragma unroll
        for (int e=0; e<4; e++) acc[nf][e]=0.f;

    const float sq0 = (float)(m0 + 16*w + g);
    const float sq1 = sq0 + 8.f;
    const int rw0 = 16*w + g;

    for (int nb=0; nb<32; nb++){
        __syncthreads();
        // K tile: [key][d] row-major, packed half2 along d
        #pragma unroll
        for (int it=0; it<2; it++){
            int l = tid + it*256;            // 0..511
            int key = l >> 4, dq = l & 15;
            float4 kv = *(const float4*)(kg + (size_t)(nb*32+key)*HD + dq*4);
            uint32_t h0,l0,h1,l1;
            split_pair(kv.x, kv.y, h0, l0);
            split_pair(kv.z, kv.w, h1, l1);
            kh[key*KS + dq*2  ] = h0; kh[key*KS + dq*2+1] = h1;
            kl[key*KS + dq*2  ] = l0; kl[key*KS + dq*2+1] = l1;
        }
        // V^T tile: 2x2 micro-transpose per thread, packed half2 along key
        #pragma unroll
        for (int it=0; it<1; it++){
            int l = tid + it*256;            // 0..255? need 512 -> use 2 elems below
        }
        #pragma unroll
        for (int it=0; it<2; it++){
            int l = tid + it*256;            // 0..511
            int dp = l & 31, kp = l >> 5;    // dp: d-pair 0..31, kp: key-pair 0..15
            float2 v0 = *(const float2*)(vg + (size_t)(nb*32 + 2*kp  )*HD + 2*dp);
            float2 v1 = *(const float2*)(vg + (size_t)(nb*32 + 2*kp+1)*HD + 2*dp);
            __half h00=__float2half_rn(v0.x), h01=__float2half_rn(v0.y);
            __half h10=__float2half_rn(v1.x), h11=__float2half_rn(v1.y);
            __half l00=__float2half_rn(v0.x-__half2float(h00));
            __half l01=__float2half_rn(v0.y-__half2float(h01));
            __half l10=__float2half_rn(v1.x-__half2float(h10));
            __half l11=__float2half_rn(v1.y-__half2float(h11));
            vth[(2*dp  )*QS + kp] = packh(h00, h10);
            vth[(2*dp+1)*QS + kp] = packh(h01, h11);
            vtl[(2*dp  )*QS + kp] = packh(l00, l10);
            vtl[(2*dp+1)*QS + kp] = packh(l01, l11);
        }
        __syncthreads();

        // QK^T: 16 x 32, k=64 (4 k16 steps), 3 MMAs per logical
        float cf[4][4];
        #pragma unroll
        for (int nf=0; nf<4; nf++){
            #pragma unroll
            for (int e=0; e<4; e++) cf[nf][e]=0.f;
            #pragma unroll
            for (int kf=0; kf<4; kf++){
                int n = nf*8 + g;
                uint32_t b0h = kh[n*KS + kf*8 + q], b1h = kh[n*KS + kf*8 + q+4];
                uint32_t b0l = kl[n*KS + kf*8 + q], b1l = kl[n*KS + kf*8 + q+4];
                mma_f16(cf[nf], qah[kf][0],qah[kf][1],qah[kf][2],qah[kf][3], b0h,b1h);
                mma_f16(cf[nf], qah[kf][0],qah[kf][1],qah[kf][2],qah[kf][3], b0l,b1l);
                mma_f16(cf[nf], qal[kf][0],qal[kf][1],qal[kf][2],qal[kf][3], b0h,b1h);
            }
        }

        // Pointwise: decay, sigmoid, w = rem_old * beta; split w into hi/lo
        float sw0=0.f, sw1=0.f, mx0=-INFINITY, mx1=-INFINITY;
        #pragma unroll
        for (int nf=0; nf<4; nf++){
            int colk = nf*8 + 2*q;
            float sk0 = (float)(nb*32 + colk);
            float sk1 = sk0 + 1.f;
            // row half 0
            {
                float raw0 = cf[nf][0] - lam*fabsf(sq0 - sk0);
                float raw1 = cf[nf][1] - lam*fabsf(sq0 - sk1);
                mx0 = fmaxf(mx0, fmaxf(raw0, raw1));
                float cl0 = fminf(fmaxf(raw0, -20.f), 20.f);
                float cl1 = fminf(fmaxf(raw1, -20.f), 20.f);
                float w0 = rem0 / (1.f + __expf(-cl0));
                float w1 = rem0 / (1.f + __expf(-cl1));
                sw0 += w0 + w1;
                uint32_t hi, lo;
                split_pair(w0, w1, hi, lo);
                wsh[rw0*QS + nf*4 + q] = hi;
                wsl[rw0*QS + nf*4 + q] = lo;
            }
            // row half 1
            {
                float raw0 = cf[nf][2] - lam*fabsf(sq1 - sk0);
                float raw1 = cf[nf][3] - lam*fabsf(sq1 - sk1);
                mx1 = fmaxf(mx1, fmaxf(raw0, raw1));
                float cl0 = fminf(fmaxf(raw0, -20.f), 20.f);
                float cl1 = fminf(fmaxf(raw1, -20.f), 20.f);
                float w0 = rem1 / (1.f + __expf(-cl0));
                float w1 = rem1 / (1.f + __expf(-cl1));
                sw1 += w0 + w1;
                uint32_t hi, lo;
                split_pair(w0, w1, hi, lo);
                wsh[(rw0+8)*QS + nf*4 + q] = hi;
                wsl[(rw0+8)*QS + nf*4 + q] = lo;
            }
        }
        #pragma unroll
        for (int ofs=2; ofs>0; ofs>>=1){
            sw0 += __shfl_xor_sync(0xffffffffu, sw0, ofs);
            sw1 += __shfl_xor_sync(0xffffffffu, sw1, ofs);
            mx0  = fmaxf(mx0, __shfl_xor_sync(0xffffffffu, mx0, ofs));
            mx1  = fmaxf(mx1, __shfl_xor_sync(0xffffffffu, mx1, ofs));
        }
        {
            float mn = fmaxf(mi0, mx0);
            li0 = li0*exp2f(mi0-mn) + sw0; mi0 = mn;
            rem0 = fmaxf(rem0*(1.f - sw0), 1e-6f);
        }
        {
            float mn = fmaxf(mi1, mx1);
            li1 = li1*exp2f(mi1-mn) + sw1; mi1 = mn;
            rem1 = fmaxf(rem1*(1.f - sw1), 1e-6f);
        }
        __syncwarp();

        // PV: acc(16 x 64) += w(16 x 32) @ V(32 x 64); 2 k16 steps
        #pragma unroll
        for (int kf=0; kf<2; kf++){
            uint32_t a0h = wsh[(rw0  )*QS + kf*8 + q  ];
            uint32_t a1h = wsh[(rw0+8)*QS + kf*8 + q  ];
            uint32_t a2h = wsh[(rw0  )*QS + kf*8 + q+4];
            uint32_t a3h = wsh[(rw0+8)*QS + kf*8 + q+4];
            uint32_t a0l = wsl[(rw0  )*QS + kf*8 + q  ];
            uint32_t a1l = wsl[(rw0+8)*QS + kf*8 + q  ];
            uint32_t a2l = wsl[(rw0  )*QS + kf*8 + q+4];
            uint32_t a3l = wsl[(rw0+8)*QS + kf*8 + q+4];
            #pragma unroll
            for (int nf=0; nf<8; nf++){
                int n = nf*8 + g;
                uint32_t b0h = vth[n*QS + kf*8 + q], b1h = vth[n*QS + kf*8 + q+4];
                uint32_t b0l = vtl[n*QS + kf*8 + q], b1l = vtl[n*QS + kf*8 + q+4];
                mma_f16(acc[nf], a0h,a1h,a2h,a3h, b0h,b1h);
                mma_f16(acc[nf], a0h,a1h,a2h,a3h, b0l,b1l);
                mma_f16(acc[nf], a0l,a1l,a2l,a3l, b0h,b1h);
            }
        }
    }

    float* og = g_o + (size_t)bh*SEQ*HD;
    const float inv0 = 1.f / fmaxf(li0, 1e-6f);
    const float inv1 = 1.f / fmaxf(li1, 1e-6f);
    const int r0 = m0 + 16*w + g;
    #pragma unroll
    for (int nf=0; nf<8; nf++){
        int col = nf*8 + 2*q;
        *(float2*)(og + (size_t)(r0  )*HD + col) =
            make_float2(acc[nf][0]*inv0, acc[nf][1]*inv0);
        *(float2*)(og + (size_t)(r0+8)*HD + col) =
            make_float2(acc[nf][2]*inv1, acc[nf][3]*inv1);
    }
}

// ---------------------------------------------------------------------------
// Output projection (split-fp16 MMA): y = ctx @ Wo^T + bo, ctx from g_o.
// grid = (128, 12), 256 threads. BM=128, BN=64, BK=32.
// ---------------------------------------------------------------------------
__global__ __launch_bounds__(256) void out_kernel(
    const float* __restrict__ Wo, const float* __restrict__ bo,
    float* __restrict__ y)
{
    __shared__ uint32_t xh[128*QS], xl[128*QS];
    __shared__ uint32_t wh[64*QS],  wl[64*QS];

    const int row0 = blockIdx.x * 128;
    const int cb   = blockIdx.y;
    const int tid  = threadIdx.x;
    const int w    = tid >> 5, lane = tid & 31;
    const int g    = lane >> 2, q = lane & 3;
    const int warpm = w >> 1, warpn = w & 1;

    float c[2][4][4];
    #pragma unroll
    for (int mf=0; mf<2; mf++)
        #pragma unroll
        for (int nf=0; nf<4; nf++)
            #pragma unroll
            for (int e=0; e<4; e++) c[mf][nf][e]=0.f;

    for (int k0 = 0; k0 < HIDN; k0 += 32) {
        #pragma unroll
        for (int it=0; it<4; it++){
            int l = tid + it*256;
            int m = l >> 3, kq = l & 7;
            int row = row0 + m;
            int b_ = row >> 10, s_ = row & 1023;
            int kcol = k0 + kq*4;
            int hh = kcol >> 6, dd = kcol & 63;
            float4 v = *(const float4*)(g_o + ((size_t)(b_*NH+hh)*SEQ + s_)*HD + dd);
            uint32_t h0,l0,h1,l1;
            split_pair(v.x, v.y, h0, l0);
            split_pair(v.z, v.w, h1, l1);
            xh[m*QS + kq*2  ] = h0; xh[m*QS + kq*2+1] = h1;
            xl[m*QS + kq*2  ] = l0; xl[m*QS + kq*2+1] = l1;
        }
        #pragma unroll
        for (int it=0; it<2; it++){
            int l = tid + it*256;
            int n = l >> 3, kq = l & 7;
            float4 v = *(const float4*)(Wo + (size_t)(cb*64+n)*HIDN + k0 + kq*4);
            uint32_t h0,l0,h1,l1;
            split_pair(v.x, v.y, h0, l0);
            split_pair(v.z, v.w, h1, l1);
            wh[n*QS + kq*2  ] = h0; wh[n*QS + kq*2+1] = h1;
            wl[n*QS + kq*2  ] = l0; wl[n*QS + kq*2+1] = l1;
        }
        __syncthreads();
        #pragma unroll
        for (int kf=0; kf<2; kf++){
            uint32_t ah[2][4], al[2][4];
            #pragma unroll
            for (int mf=0; mf<2; mf++){
                int r = warpm*32 + mf*16 + g;
                ah[mf][0]=xh[(r  )*QS + kf*8 + q  ]; ah[mf][1]=xh[(r+8)*QS + kf*8 + q  ];
                ah[mf][2]=xh[(r  )*QS + kf*8 + q+4]; ah[mf][3]=xh[(r+8)*QS + kf*8 + q+4];
                al[mf][0]=xl[(r  )*QS + kf*8 + q  ]; al[mf][1]=xl[(r+8)*QS + kf*8 + q  ];
                al[mf][2]=xl[(r  )*QS + kf*8 + q+4]; al[mf][3]=xl[(r+8)*QS + kf*8 + q+4];
            }
            uint32_t bh[4][2], bl[4][2];
            #pragma unroll
            for (int nf=0; nf<4; nf++){
                int n = warpn*32 + nf*8 + g;
                bh[nf][0]=wh[n*QS + kf*8 + q]; bh[nf][1]=wh[n*QS + kf*8 + q+4];
                bl[nf][0]=wl[n*QS + kf*8 + q]; bl[nf][1]=wl[n*QS + kf*8 + q+4];
            }
            #pragma unroll
            for (int mf=0; mf<2; mf++)
                #pragma unroll
                for (int nf=0; nf<4; nf++){
                    mma_f16(c[mf][nf], ah[mf][0],ah[mf][1],ah[mf][2],ah[mf][3], bh[nf][0],bh[nf][1]);
                    mma_f16(c[mf][nf], ah[mf][0],ah[mf][1],ah[mf][2],ah[mf][3], bl[nf][0],bl[nf][1]);
                    mma_f16(c[mf][nf], al[mf][0],al[mf][1],al[mf][2],al[mf][3], bh[nf][0],bh[nf][1]);
                }
        }
        __syncthreads();
    }

    #pragma unroll
    for (int nf=0; nf<4; nf++){
        int col = cb*64 + warpn*32 + nf*8 + 2*q;
        float b0 = bo[col], b1 = bo[col+1];
        #pragma unroll
        for (int mf=0; mf<2; mf++){
            #pragma unroll
            for (int half=0; half<2; half++){
                int row = row0 + warpm*32 + mf*16 + g + half*8;
                *(float2*)(y + (size_t)row*HIDN + col) =
                    make_float2(c[mf][nf][half*2+0] + b0,
                                c[mf][nf][half*2+1] + b1);
            }
        }
    }
}

// ---------------------------------------------------------------------------
extern "C" void kernel_launch(void* const* d_in, const int* in_sizes, int n_in,
                              void* d_out, int out_size)
{
    const float* x    = (const float*)d_in[0];
    const float* Wq   = (const float*)d_in[1];
    const float* bq   = (const float*)d_in[2];
    const float* Wk   = (const float*)d_in[3];
    const float* bk   = (const float*)d_in[4];
    const float* Wv   = (const float*)d_in[5];
    const float* bv   = (const float*)d_in[6];
    const float* Wo   = (const float*)d_in[7];
    const float* bo   = (const float*)d_in[8];
    const float* lam  = (const float*)d_in[9];
    const float* cosc = (const float*)d_in[10];
    const float* sinc = (const float*)d_in[11];
    float* y = (float*)d_out;

    dim3 g1(BDIM*SEQ/128, NH, 3);
    qkv_kernel<<<g1, 256>>>(x, Wq, bq, Wk, bk, Wv, bv, cosc, sinc);

    dim3 g2(SEQ/128, NBH);
    attn_kernel<<<g2, 256>>>(lam);

    dim3 g3(BDIM*SEQ/128, NH);
    out_kernel<<<g3, 256>>>(Wo, bo, y);
}